// round 6
// baseline (speedup 1.0000x reference)
#include <cuda_runtime.h>

#define NN 50000
#define EE 400000
#define HH 128
#define NREL 20
#define CH 512
#define SWP 20   // padded smem row stride (floats) for conflict-free STS.128/LDS.128

// Scratch (device globals; no allocation allowed)
__device__ float  g_deg[2 * NREL * NN];    // degrees -> rsqrt-normalized in place (ns/nd)
__device__ float  g_v[NREL * NN];          // v_r[s] = sum_e nd_r[d]
__device__ float4 g_u4[5 * NN];            // u packed per dst type: .j = u_{4g+j}[n]
__device__ float4 g_ut4[NREL * NN];        // ut_rp[d] = nd_rp[d] * u4[dst(rp)][d]
__device__ float4 g_wt4[NREL * NN];        // wt_rp[s] = sum_e ut_rp[d]
__device__ float  g_sigma[NREL];           // sigma_r = sum_n ns_r[n]*v_r[n]
__device__ float  g_y[80 * 768];           // y[(rp*4 + j)][c] = w^T x
__device__ float  g_t[NREL * HH];          // t_r

// RELS dst ntype ids (stock=0, financial=1, macro=2, news=3, policy=4)
__constant__ int c_dst[NREL] = {1,2,3,4, 2,0,3,4, 0,1,3,4, 0,1,2,4, 0,2,3,1};
__constant__ int c_inrel[5][4] = {{5,8,12,16},{0,9,13,19},{1,4,14,17},{2,6,10,18},{3,7,11,15}};
__constant__ int c_F[5] = {5,16,21,768,768};

__global__ void k_zero() {
    int i = blockIdx.x * blockDim.x + threadIdx.x;
    int stride = gridDim.x * blockDim.x;
    float4 z = make_float4(0.f, 0.f, 0.f, 0.f);
    for (int k = i; k < (2 * NREL * NN) / 4; k += stride) ((float4*)g_deg)[k] = z;
    for (int k = i; k < (NREL * NN) / 4; k += stride) ((float4*)g_v)[k] = z;
    for (int k = i; k < NREL * NN; k += stride) g_wt4[k] = z;
    for (int k = i; k < (80 * 768) / 4; k += stride) ((float4*)g_y)[k] = z;
    for (int k = i; k < (NREL * HH) / 4; k += stride) ((float4*)g_t)[k] = z;
    if (i < NREL) g_sigma[i] = 0.f;
}

__global__ void k_degree(const int* __restrict__ edges) {
    int t = blockIdx.x * blockDim.x + threadIdx.x;
    if (t >= EE / 4) return;
    int r = blockIdx.y;
    const int4* sp = (const int4*)(edges + r * 2 * EE);
    const int4* dp = (const int4*)(edges + r * 2 * EE + EE);
    int4 s = sp[t], d = dp[t];
    float* ds = g_deg + (2 * r) * NN;
    float* dd = ds + NN;
    atomicAdd(&ds[s.x], 1.f); atomicAdd(&ds[s.y], 1.f);
    atomicAdd(&ds[s.z], 1.f); atomicAdd(&ds[s.w], 1.f);
    atomicAdd(&dd[d.x], 1.f); atomicAdd(&dd[d.y], 1.f);
    atomicAdd(&dd[d.z], 1.f); atomicAdd(&dd[d.w], 1.f);
}

// in-place: deg -> rsqrt(max(deg,1))
__global__ void k_norm() {
    int i = blockIdx.x * blockDim.x + threadIdx.x;
    int stride = gridDim.x * blockDim.x;
    float4* p = (float4*)g_deg;
    for (int k = i; k < (2 * NREL * NN) / 4; k += stride) {
        float4 v = p[k];
        v.x = rsqrtf(fmaxf(v.x, 1.f));
        v.y = rsqrtf(fmaxf(v.y, 1.f));
        v.z = rsqrtf(fmaxf(v.z, 1.f));
        v.w = rsqrtf(fmaxf(v.w, 1.f));
        p[k] = v;
    }
}

// v_r[s] += nd_r[d]   (1 gather + 1 RED per edge)
__global__ void k_vpass(const int* __restrict__ edges) {
    int t = blockIdx.x * blockDim.x + threadIdx.x;
    if (t >= EE / 4) return;
    int r = blockIdx.y;
    const int4* sp = (const int4*)(edges + r * 2 * EE);
    const int4* dp = (const int4*)(edges + r * 2 * EE + EE);
    int4 s4 = sp[t], d4 = dp[t];
    const float* nd_ = g_deg + (2 * r + 1) * NN;
    float* v = g_v + r * NN;
    atomicAdd(&v[s4.x], nd_[d4.x]);
    atomicAdd(&v[s4.y], nd_[d4.y]);
    atomicAdd(&v[s4.z], nd_[d4.z]);
    atomicAdd(&v[s4.w], nd_[d4.w]);
}

// streaming: u4[g][n].j = ns_{4g+j}[n]*v_{4g+j}[n]; ut_rp[n] = nd_rp[n]*u4[dst(rp)][n]
__global__ void k_uprep() {
    int n = blockIdx.x * blockDim.x + threadIdx.x;
    if (n >= NN) return;
    int g = blockIdx.y;  // dst type 0..4
    float4 u;
    u.x = g_deg[(2 * (4 * g + 0)) * NN + n] * g_v[(4 * g + 0) * NN + n];
    u.y = g_deg[(2 * (4 * g + 1)) * NN + n] * g_v[(4 * g + 1) * NN + n];
    u.z = g_deg[(2 * (4 * g + 2)) * NN + n] * g_v[(4 * g + 2) * NN + n];
    u.w = g_deg[(2 * (4 * g + 3)) * NN + n] * g_v[(4 * g + 3) * NN + n];
    g_u4[g * NN + n] = u;
}

__global__ void k_utld() {
    int n = blockIdx.x * blockDim.x + threadIdx.x;
    if (n >= NN) return;
    int rp = blockIdx.y;
    int dt = c_dst[rp];
    float nd = g_deg[(2 * rp + 1) * NN + n];
    float4 u = g_u4[dt * NN + n];
    g_ut4[rp * NN + n] = make_float4(nd * u.x, nd * u.y, nd * u.z, nd * u.w);
}

// sigma_r = sum_n ns_r[n]*v_r[n]
__global__ void k_sigma() {
    int r = blockIdx.x;
    int i0 = blockIdx.y * 6250;
    int i1 = min(i0 + 6250, NN);
    const float* ns_ = g_deg + (2 * r) * NN;
    const float* v = g_v + r * NN;
    float a = 0.f;
    for (int i = i0 + threadIdx.x; i < i1; i += blockDim.x) a += ns_[i] * v[i];
    __shared__ float sred[256];
    sred[threadIdx.x] = a;
    __syncthreads();
    for (int st = 128; st > 0; st >>= 1) {
        if (threadIdx.x < st) sred[threadIdx.x] += sred[threadIdx.x + st];
        __syncthreads();
    }
    if (threadIdx.x == 0) atomicAdd(&g_sigma[r], sred[0]);
}

// wt_rp[s] += ut_rp[d]   (one 16B gather + one 16B RED per edge, no math)
__global__ void k_wpass(const int* __restrict__ edges) {
    int t = blockIdx.x * blockDim.x + threadIdx.x;
    if (t >= EE / 4) return;
    int rp = blockIdx.y;
    const int4* sp = (const int4*)(edges + rp * 2 * EE);
    const int4* dp = (const int4*)(edges + rp * 2 * EE + EE);
    int4 s4 = sp[t], d4 = dp[t];
    const float4* ut = g_ut4 + rp * NN;
    float4* wt = g_wt4 + rp * NN;
    atomicAdd(&wt[s4.x], ut[d4.x]);
    atomicAdd(&wt[s4.y], ut[d4.y]);
    atomicAdd(&wt[s4.z], ut[d4.z]);
    atomicAdd(&wt[s4.w], ut[d4.w]);
}

// y[16S + p][c] += sum_u (ns*wt)[p][u] * x_S[u][c]; ns fold in the smem loader.
// grid: (1, ceil(NN/CH), 5), block 256; 4 cols/thread.
__global__ void k_colsum(const float* __restrict__ xs, const float* __restrict__ xf,
                         const float* __restrict__ xm, const float* __restrict__ xn,
                         const float* __restrict__ xp) {
    int S = blockIdx.z;
    int F = c_F[S];
    const float* xtab[5] = {xs, xf, xm, xn, xp};
    const float* x = xtab[S];
    int c0 = threadIdx.x * 4;
    int u0 = blockIdx.y * CH;
    int u1 = min(u0 + CH, NN);
    bool vec = ((F & 3) == 0);
    bool active = (c0 < F);
    __shared__ float sw[64 * SWP];   // [node][16 p], padded row
    float acc[64];
#pragma unroll
    for (int k = 0; k < 64; k++) acc[k] = 0.f;
    for (int ub = u0; ub < u1; ub += 64) {
        int cnt = min(64, u1 - ub);
        {
            int i = threadIdx.x;    // 256 threads: rl = i>>6 (4 rels), ii = i&63 (64 nodes)
            int rl = i >> 6, ii = i & 63;
            int rp = 4 * S + rl;
            float4 v = make_float4(0.f, 0.f, 0.f, 0.f);
            if (ii < cnt) {
                int node = ub + ii;
                float ns = g_deg[(2 * rp) * NN + node];
                float4 wt = g_wt4[rp * NN + node];
                v = make_float4(ns * wt.x, ns * wt.y, ns * wt.z, ns * wt.w);
            }
            *(float4*)&sw[ii * SWP + rl * 4] = v;
        }
        __syncthreads();
        if (active) {
            if (vec) {
                const float* xr = x + (size_t)ub * F + c0;
#pragma unroll 2
                for (int i = 0; i < 64; i++) {
                    if (i >= cnt) break;
                    float4 xv = *(const float4*)(xr + (size_t)i * F);
                    const float4* swr = (const float4*)&sw[i * SWP];
#pragma unroll
                    for (int pg = 0; pg < 4; pg++) {
                        float4 s4 = swr[pg];
                        float sv[4] = {s4.x, s4.y, s4.z, s4.w};
#pragma unroll
                        for (int q = 0; q < 4; q++) {
                            int p = pg * 4 + q;
                            acc[p * 4 + 0] += sv[q] * xv.x;
                            acc[p * 4 + 1] += sv[q] * xv.y;
                            acc[p * 4 + 2] += sv[q] * xv.z;
                            acc[p * 4 + 3] += sv[q] * xv.w;
                        }
                    }
                }
            } else {
                for (int i = 0; i < cnt; i++) {
                    const float* xr = x + (size_t)(ub + i) * F;
                    float xv[4];
#pragma unroll
                    for (int v2 = 0; v2 < 4; v2++)
                        xv[v2] = (c0 + v2 < F) ? xr[c0 + v2] : 0.f;
#pragma unroll
                    for (int p = 0; p < 16; p++) {
                        float s = sw[i * SWP + p];
                        acc[p * 4 + 0] += s * xv[0];
                        acc[p * 4 + 1] += s * xv[1];
                        acc[p * 4 + 2] += s * xv[2];
                        acc[p * 4 + 3] += s * xv[3];
                    }
                }
            }
        }
        __syncthreads();
    }
    if (active) {
#pragma unroll
        for (int p = 0; p < 16; p++) {
#pragma unroll
            for (int v2 = 0; v2 < 4; v2++) {
                if (c0 + v2 < F)
                    atomicAdd(&g_y[(16 * S + p) * 768 + c0 + v2], acc[p * 4 + v2]);
            }
        }
    }
}

// t_r[j] += (y_{(r,rp)} @ W1_{rp})[j] + sigma_r * b1[rp][j]
__global__ void k_combine(const float* __restrict__ w1s, const float* __restrict__ w1f,
                          const float* __restrict__ w1m, const float* __restrict__ w1n,
                          const float* __restrict__ w1p, const float* __restrict__ b1) {
    int r = blockIdx.x, q = blockIdx.y, j = threadIdx.x;
    const float* W1tab[5] = {w1s, w1f, w1m, w1n, w1p};
    int s = r >> 2;
    int rp = c_inrel[s][q];
    int S2 = rp >> 2;
    int F = c_F[S2];
    const float* W1 = W1tab[S2] + (rp & 3) * F * HH;
    const float* y = &g_y[(rp * 4 + (r & 3)) * 768];
    float a = 0.f;
    for (int cc = 0; cc < F; cc++) a += y[cc] * W1[cc * HH + j];
    a += g_sigma[r] * b1[rp * HH + j];
    atomicAdd(&g_t[r * HH + j], a);
}

// m[j] = (1/5N) sum_r (t_r @ W2_r)[j] + (1/5) sum_r b2[r][j];  out = m@Wfc + bfc
__global__ void k_final(const float* __restrict__ W2, const float* __restrict__ b2,
                        const float* __restrict__ Wfc, const float* __restrict__ bfc,
                        float* __restrict__ out) {
    __shared__ float sm[HH];
    int j = threadIdx.x;
    float acc = 0.f, bsum = 0.f;
    for (int r = 0; r < NREL; r++) {
        const float* t = &g_t[r * HH];
        const float* W = W2 + r * HH * HH;
        float a = 0.f;
        for (int k = 0; k < HH; k++) a += t[k] * W[k * HH + j];
        acc += a;
        bsum += b2[r * HH + j];
    }
    float m = acc * (1.f / (5.f * (float)NN)) + bsum * 0.2f;
    sm[j] = m;
    out[j] = m;
    __syncthreads();
    if (j < 10) {
        float o = bfc[j];
        for (int k = 0; k < HH; k++) o += sm[k] * Wfc[k * 10 + j];
        out[HH + j] = o;
    }
}

extern "C" void kernel_launch(void* const* d_in, const int* in_sizes, int n_in,
                              void* d_out, int out_size) {
    const float* xs = (const float*)d_in[0];
    const float* xf = (const float*)d_in[1];
    const float* xm = (const float*)d_in[2];
    const float* xn = (const float*)d_in[3];
    const float* xp = (const float*)d_in[4];
    const float* w1s = (const float*)d_in[5];
    const float* w1f = (const float*)d_in[6];
    const float* w1m = (const float*)d_in[7];
    const float* w1n = (const float*)d_in[8];
    const float* w1p = (const float*)d_in[9];
    const float* b1  = (const float*)d_in[10];
    const float* W2  = (const float*)d_in[11];
    const float* b2  = (const float*)d_in[12];
    const float* Wfc = (const float*)d_in[13];
    const float* bfc = (const float*)d_in[14];
    const int* edges = (const int*)d_in[15];
    float* out = (float*)d_out;

    k_zero<<<2048, 256>>>();

    dim3 ge((EE / 4 + 255) / 256, NREL);
    k_degree<<<ge, 256>>>(edges);
    k_norm<<<2048, 256>>>();
    k_vpass<<<ge, 256>>>(edges);

    dim3 gn((NN + 255) / 256, 5);
    k_uprep<<<gn, 256>>>();
    dim3 gu((NN + 255) / 256, NREL);
    k_utld<<<gu, 256>>>();
    k_sigma<<<dim3(NREL, 8), 256>>>();

    k_wpass<<<ge, 256>>>(edges);

    dim3 gc(1, (NN + CH - 1) / CH, 5);
    k_colsum<<<gc, 256>>>(xs, xf, xm, xn, xp);

    k_combine<<<dim3(NREL, 4), HH>>>(w1s, w1f, w1m, w1n, w1p, b1);
    k_final<<<1, HH>>>(W2, b2, Wfc, bfc, out);
}

// round 8
// speedup vs baseline: 1.3843x; 1.3843x over previous
#include <cuda_runtime.h>

#define NN 50000
#define EE 400000
#define HH 128
#define NREL 20
#define CH 512
#define SWP 20   // padded smem row stride (floats)

// Scratch (device globals; no allocation allowed)
__device__ float  g_nd[NREL * NN];         // dst in-degree -> rsqrt-normalized in place
__device__ float2 g_vc[NREL * NN];         // (v_r[s] = sum_e nd[d], out-degree count)
__device__ float  g_ns[NREL * NN];         // ns_r[s] = rsqrt(max(outdeg,1))
__device__ float4 g_u4[5 * NN];            // u packed per dst type: .j = u_{4g+j}[n]
__device__ float4 g_ut4[NREL * NN];        // ut_rp[d] = nd_rp[d] * u4[dst(rp)][d]
__device__ float4 g_wt4[NREL * NN];        // wt_rp[s] = sum_e ut_rp[d]
__device__ float  g_sigma[NREL];           // sigma_r = sum_n u_r[n]
__device__ float  g_y[80 * 768];           // y[(rp*4 + j)][c] = w^T x
__device__ float  g_t[NREL * HH];          // t_r
__device__ float  g_m[HH];                 // unscaled sum over r of t_r @ W2_r

// RELS dst ntype ids (stock=0, financial=1, macro=2, news=3, policy=4)
__constant__ int c_dst[NREL] = {1,2,3,4, 2,0,3,4, 0,1,3,4, 0,1,2,4, 0,2,3,1};
__constant__ int c_inrel[5][4] = {{5,8,12,16},{0,9,13,19},{1,4,14,17},{2,6,10,18},{3,7,11,15}};
__constant__ int c_F[5] = {5,16,21,768,768};

__global__ void k_zero() {
    int i = blockIdx.x * blockDim.x + threadIdx.x;
    int stride = gridDim.x * blockDim.x;
    float4 z = make_float4(0.f, 0.f, 0.f, 0.f);
    for (int k = i; k < (NREL * NN) / 4; k += stride) ((float4*)g_nd)[k] = z;
    for (int k = i; k < (NREL * NN) / 2; k += stride) ((float4*)g_vc)[k] = z;
    for (int k = i; k < NREL * NN; k += stride) g_wt4[k] = z;
    for (int k = i; k < (80 * 768) / 4; k += stride) ((float4*)g_y)[k] = z;
    for (int k = i; k < (NREL * HH) / 4; k += stride) ((float4*)g_t)[k] = z;
    for (int k = i; k < HH / 4; k += stride) ((float4*)g_m)[k] = z;
    if (i < NREL) g_sigma[i] = 0.f;
}

// dst in-degree only (1 RED per edge)
__global__ void k_ddeg(const int* __restrict__ edges) {
    int t = blockIdx.x * blockDim.x + threadIdx.x;
    if (t >= EE / 4) return;
    int r = blockIdx.y;
    const int4* dp = (const int4*)(edges + r * 2 * EE + EE);
    int4 d = dp[t];
    float* dd = g_nd + r * NN;
    atomicAdd(&dd[d.x], 1.f); atomicAdd(&dd[d.y], 1.f);
    atomicAdd(&dd[d.z], 1.f); atomicAdd(&dd[d.w], 1.f);
}

// in-place: nd -> rsqrt(max(nd,1))
__global__ void k_normd() {
    int i = blockIdx.x * blockDim.x + threadIdx.x;
    int stride = gridDim.x * blockDim.x;
    float4* p = (float4*)g_nd;
    for (int k = i; k < (NREL * NN) / 4; k += stride) {
        float4 v = p[k];
        v.x = rsqrtf(fmaxf(v.x, 1.f));
        v.y = rsqrtf(fmaxf(v.y, 1.f));
        v.z = rsqrtf(fmaxf(v.z, 1.f));
        v.w = rsqrtf(fmaxf(v.w, 1.f));
        p[k] = v;
    }
}

// (v,cnt)[s] += (nd[d], 1)   (1 gather + 1 RED.64 per edge)
__global__ void k_vpass(const int* __restrict__ edges) {
    int t = blockIdx.x * blockDim.x + threadIdx.x;
    if (t >= EE / 4) return;
    int r = blockIdx.y;
    const int4* sp = (const int4*)(edges + r * 2 * EE);
    const int4* dp = (const int4*)(edges + r * 2 * EE + EE);
    int4 s4 = sp[t], d4 = dp[t];
    const float* nd_ = g_nd + r * NN;
    float2* vc = g_vc + r * NN;
    atomicAdd(&vc[s4.x], make_float2(nd_[d4.x], 1.f));
    atomicAdd(&vc[s4.y], make_float2(nd_[d4.y], 1.f));
    atomicAdd(&vc[s4.z], make_float2(nd_[d4.z], 1.f));
    atomicAdd(&vc[s4.w], make_float2(nd_[d4.w], 1.f));
}

// streaming: ns = rsqrt(max(cnt,1)); u4[g][n].j = ns*v; store ns for colsum
__global__ void k_prep() {
    int n = blockIdx.x * blockDim.x + threadIdx.x;
    if (n >= NN) return;
    int g = blockIdx.y;  // dst type 0..4
    float u[4];
#pragma unroll
    for (int j = 0; j < 4; j++) {
        int rp = 4 * g + j;
        float2 vc = g_vc[rp * NN + n];
        float ns = rsqrtf(fmaxf(vc.y, 1.f));
        g_ns[rp * NN + n] = ns;
        u[j] = ns * vc.x;
    }
    g_u4[g * NN + n] = make_float4(u[0], u[1], u[2], u[3]);
}

// ut_rp[n] = nd_rp[n] * u4[dst(rp)][n]  (streaming)
__global__ void k_utld() {
    int n = blockIdx.x * blockDim.x + threadIdx.x;
    if (n >= NN) return;
    int rp = blockIdx.y;
    int dt = c_dst[rp];
    float nd = g_nd[rp * NN + n];
    float4 u = g_u4[dt * NN + n];
    g_ut4[rp * NN + n] = make_float4(nd * u.x, nd * u.y, nd * u.z, nd * u.w);
}

// sigma_{4g+j} = sum_n u4[g][n].j
__global__ void k_sigma() {
    int g = blockIdx.x;
    int i0 = blockIdx.y * 6250;
    int i1 = min(i0 + 6250, NN);
    float4 a = make_float4(0.f, 0.f, 0.f, 0.f);
    for (int i = i0 + threadIdx.x; i < i1; i += blockDim.x) {
        float4 u = g_u4[g * NN + i];
        a.x += u.x; a.y += u.y; a.z += u.z; a.w += u.w;
    }
    __shared__ float4 sred[256];
    sred[threadIdx.x] = a;
    __syncthreads();
    for (int st = 128; st > 0; st >>= 1) {
        if (threadIdx.x < st) {
            float4 b = sred[threadIdx.x + st];
            sred[threadIdx.x].x += b.x; sred[threadIdx.x].y += b.y;
            sred[threadIdx.x].z += b.z; sred[threadIdx.x].w += b.w;
        }
        __syncthreads();
    }
    if (threadIdx.x == 0) {
        float4 s = sred[0];
        atomicAdd(&g_sigma[4 * g + 0], s.x);
        atomicAdd(&g_sigma[4 * g + 1], s.y);
        atomicAdd(&g_sigma[4 * g + 2], s.z);
        atomicAdd(&g_sigma[4 * g + 3], s.w);
    }
}

// wt_rp[s] += ut_rp[d]   (one 16B gather + one 16B RED per edge)
__global__ void k_wpass(const int* __restrict__ edges) {
    int t = blockIdx.x * blockDim.x + threadIdx.x;
    if (t >= EE / 4) return;
    int rp = blockIdx.y;
    const int4* sp = (const int4*)(edges + rp * 2 * EE);
    const int4* dp = (const int4*)(edges + rp * 2 * EE + EE);
    int4 s4 = sp[t], d4 = dp[t];
    const float4* ut = g_ut4 + rp * NN;
    float4* wt = g_wt4 + rp * NN;
    atomicAdd(&wt[s4.x], ut[d4.x]);
    atomicAdd(&wt[s4.y], ut[d4.y]);
    atomicAdd(&wt[s4.z], ut[d4.z]);
    atomicAdd(&wt[s4.w], ut[d4.w]);
}

// y[16S + p][c] += sum_u (ns*wt)[p][u] * x_S[u][c]; ns folded in the smem loader.
__global__ void k_colsum(const float* __restrict__ xs, const float* __restrict__ xf,
                         const float* __restrict__ xm, const float* __restrict__ xn,
                         const float* __restrict__ xp) {
    int S = blockIdx.z;
    int F = c_F[S];
    const float* xtab[5] = {xs, xf, xm, xn, xp};
    const float* x = xtab[S];
    int c0 = threadIdx.x * 4;
    int u0 = blockIdx.y * CH;
    int u1 = min(u0 + CH, NN);
    bool vec = ((F & 3) == 0);
    bool active = (c0 < F);
    __shared__ float sw[64 * SWP];   // [node][16 p], padded row
    float acc[64];
#pragma unroll
    for (int k = 0; k < 64; k++) acc[k] = 0.f;
    for (int ub = u0; ub < u1; ub += 64) {
        int cnt = min(64, u1 - ub);
        {
            int i = threadIdx.x;    // rl = i>>6 (4 rels), ii = i&63 (64 nodes)
            int rl = i >> 6, ii = i & 63;
            int rp = 4 * S + rl;
            float4 v = make_float4(0.f, 0.f, 0.f, 0.f);
            if (ii < cnt) {
                int node = ub + ii;
                float ns = g_ns[rp * NN + node];
                float4 wt = g_wt4[rp * NN + node];
                v = make_float4(ns * wt.x, ns * wt.y, ns * wt.z, ns * wt.w);
            }
            *(float4*)&sw[ii * SWP + rl * 4] = v;
        }
        __syncthreads();
        if (active) {
            if (vec) {
                const float* xr = x + (size_t)ub * F + c0;
#pragma unroll 2
                for (int i = 0; i < 64; i++) {
                    if (i >= cnt) break;
                    float4 xv = *(const float4*)(xr + (size_t)i * F);
                    const float4* swr = (const float4*)&sw[i * SWP];
#pragma unroll
                    for (int pg = 0; pg < 4; pg++) {
                        float4 s4 = swr[pg];
                        float sv[4] = {s4.x, s4.y, s4.z, s4.w};
#pragma unroll
                        for (int q = 0; q < 4; q++) {
                            int p = pg * 4 + q;
                            acc[p * 4 + 0] += sv[q] * xv.x;
                            acc[p * 4 + 1] += sv[q] * xv.y;
                            acc[p * 4 + 2] += sv[q] * xv.z;
                            acc[p * 4 + 3] += sv[q] * xv.w;
                        }
                    }
                }
            } else {
                for (int i = 0; i < cnt; i++) {
                    const float* xr = x + (size_t)(ub + i) * F;
                    float xv[4];
#pragma unroll
                    for (int v2 = 0; v2 < 4; v2++)
                        xv[v2] = (c0 + v2 < F) ? xr[c0 + v2] : 0.f;
#pragma unroll
                    for (int p = 0; p < 16; p++) {
                        float s = sw[i * SWP + p];
                        acc[p * 4 + 0] += s * xv[0];
                        acc[p * 4 + 1] += s * xv[1];
                        acc[p * 4 + 2] += s * xv[2];
                        acc[p * 4 + 3] += s * xv[3];
                    }
                }
            }
        }
        __syncthreads();
    }
    if (active) {
#pragma unroll
        for (int p = 0; p < 16; p++) {
#pragma unroll
            for (int v2 = 0; v2 < 4; v2++) {
                if (c0 + v2 < F)
                    atomicAdd(&g_y[(16 * S + p) * 768 + c0 + v2], acc[p * 4 + v2]);
            }
        }
    }
}

// t_r[j] += (y_{(r,rp)} @ W1_{rp})[j] + sigma_r * b1[rp][j]
__global__ void k_combine(const float* __restrict__ w1s, const float* __restrict__ w1f,
                          const float* __restrict__ w1m, const float* __restrict__ w1n,
                          const float* __restrict__ w1p, const float* __restrict__ b1) {
    int r = blockIdx.x, q = blockIdx.y, j = threadIdx.x;
    const float* W1tab[5] = {w1s, w1f, w1m, w1n, w1p};
    int s = r >> 2;
    int rp = c_inrel[s][q];
    int S2 = rp >> 2;
    int F = c_F[S2];
    const float* W1 = W1tab[S2] + (rp & 3) * F * HH;
    const float* y = &g_y[(rp * 4 + (r & 3)) * 768];
    float a = 0.f;
    for (int cc = 0; cc < F; cc++) a += y[cc] * W1[cc * HH + j];
    a += g_sigma[r] * b1[rp * HH + j];
    atomicAdd(&g_t[r * HH + j], a);
}

// g_m[j] += (t_r @ W2_r)[j], one block per relation (coalesced W2 rows)
__global__ void k_mpart(const float* __restrict__ W2) {
    int r = blockIdx.x, j = threadIdx.x;
    __shared__ float st[HH];
    st[j] = g_t[r * HH + j];
    __syncthreads();
    const float* W = W2 + r * HH * HH;
    float a = 0.f;
#pragma unroll 4
    for (int k = 0; k < HH; k++) a += st[k] * W[k * HH + j];
    atomicAdd(&g_m[j], a);
}

// m[j] = g_m[j]/(5N) + 0.2*sum_r b2[r][j];  out = [m, m@Wfc + bfc]
__global__ void k_fc(const float* __restrict__ b2, const float* __restrict__ Wfc,
                     const float* __restrict__ bfc, float* __restrict__ out) {
    __shared__ float sm[HH];
    int j = threadIdx.x;
    float bsum = 0.f;
    for (int r = 0; r < NREL; r++) bsum += b2[r * HH + j];
    float m = g_m[j] * (1.f / (5.f * (float)NN)) + bsum * 0.2f;
    sm[j] = m;
    out[j] = m;
    __syncthreads();
    if (j < 10) {
        float o = bfc[j];
        for (int k = 0; k < HH; k++) o += sm[k] * Wfc[k * 10 + j];
        out[HH + j] = o;
    }
}

extern "C" void kernel_launch(void* const* d_in, const int* in_sizes, int n_in,
                              void* d_out, int out_size) {
    const float* xs = (const float*)d_in[0];
    const float* xf = (const float*)d_in[1];
    const float* xm = (const float*)d_in[2];
    const float* xn = (const float*)d_in[3];
    const float* xp = (const float*)d_in[4];
    const float* w1s = (const float*)d_in[5];
    const float* w1f = (const float*)d_in[6];
    const float* w1m = (const float*)d_in[7];
    const float* w1n = (const float*)d_in[8];
    const float* w1p = (const float*)d_in[9];
    const float* b1  = (const float*)d_in[10];
    const float* W2  = (const float*)d_in[11];
    const float* b2  = (const float*)d_in[12];
    const float* Wfc = (const float*)d_in[13];
    const float* bfc = (const float*)d_in[14];
    const int* edges = (const int*)d_in[15];
    float* out = (float*)d_out;

    k_zero<<<2048, 256>>>();

    dim3 ge((EE / 4 + 255) / 256, NREL);
    k_ddeg<<<ge, 256>>>(edges);
    k_normd<<<1024, 256>>>();
    k_vpass<<<ge, 256>>>(edges);

    dim3 gn((NN + 255) / 256, 5);
    k_prep<<<gn, 256>>>();
    dim3 gu((NN + 255) / 256, NREL);
    k_utld<<<gu, 256>>>();
    k_sigma<<<dim3(5, 8), 256>>>();

    k_wpass<<<ge, 256>>>(edges);

    dim3 gc(1, (NN + CH - 1) / CH, 5);
    k_colsum<<<gc, 256>>>(xs, xf, xm, xn, xp);

    k_combine<<<dim3(NREL, 4), HH>>>(w1s, w1f, w1m, w1n, w1p, b1);
    k_mpart<<<NREL, HH>>>(W2);
    k_fc<<<1, HH>>>(b2, Wfc, bfc, out);
}